// round 14
// baseline (speedup 1.0000x reference)
#include <cuda_runtime.h>
#include <cuda_fp16.h>

// NeighborhoodAttention 3D, NATTEN clamped window (3,7,7).
// B=1, T=16, H=32, W=32, nh=8, D=128, fp32.
//
// Round 14 = Round 13 (QK tensor-core, q hi/lo exact x K_hi f16; max-free
// softmax; PV exact fp32 packed fma.rn.f32x2) plus:
//  - 32-thread CTAs (warps are independent) -> no CTA reg-granularity loss
//  - QK software pipeline: e[s] refilled for chunk c+1 right after chunk c's
//    MMA consumes it (zero extra registers, hides cross-chunk LDG latency)
//  - incremental halo trackers instead of div/mod per chunk

#define T_  16
#define H_  32
#define W_  32
#define NH  8
#define L_  16384
#define ROW4 256
#define QK_SCALE (0.08838834764831845f * 1.4426950408889634f)  // /sqrt(128)*log2e

// K_hi packed: index ((head*8 + s)*L + l)*4 + p, uint2 = {b0, b1} of one MMA
__device__ uint2 g_kh[(size_t)NH * 8 * L_ * 4];   // 32 MB

__global__ __launch_bounds__(256)
void prep_kh(const float* __restrict__ K)
{
    const int tid = blockIdx.x * 256 + threadIdx.x;   // 1,048,576 threads
    const int l    = tid & (L_ - 1);
    const int hs   = tid >> 14;            // head*8 + s
    const int head = hs >> 3;
    const int s    = hs & 7;
    const float* src = K + ((size_t)l << 10) + (head << 7) + (s << 4);
    const float4 f0 = *(const float4*)(src);
    const float4 f1 = *(const float4*)(src + 4);
    const float4 f2 = *(const float4*)(src + 8);
    const float4 f3 = *(const float4*)(src + 12);

    uint2 e[4];
    __half2 h;
    h = __floats2half2_rn(f0.x, f0.y); e[0].x = *(unsigned*)&h;
    h = __floats2half2_rn(f2.x, f2.y); e[0].y = *(unsigned*)&h;
    h = __floats2half2_rn(f0.z, f0.w); e[1].x = *(unsigned*)&h;
    h = __floats2half2_rn(f2.z, f2.w); e[1].y = *(unsigned*)&h;
    h = __floats2half2_rn(f1.x, f1.y); e[2].x = *(unsigned*)&h;
    h = __floats2half2_rn(f3.x, f3.y); e[2].y = *(unsigned*)&h;
    h = __floats2half2_rn(f1.z, f1.w); e[3].x = *(unsigned*)&h;
    h = __floats2half2_rn(f3.z, f3.w); e[3].y = *(unsigned*)&h;

    uint4* dst = (uint4*)(g_kh + (size_t)tid * 4);
    dst[0] = *(uint4*)&e[0];
    dst[1] = *(uint4*)&e[2];
}

static __device__ __forceinline__ void mma16816(
    float& c0, float& c1, float& c2, float& c3,
    unsigned a0, unsigned a1, unsigned a2, unsigned a3,
    unsigned b0, unsigned b1)
{
    asm volatile("mma.sync.aligned.m16n8k16.row.col.f32.f16.f16.f32 "
                 "{%0,%1,%2,%3}, {%4,%5,%6,%7}, {%8,%9}, {%0,%1,%2,%3};"
                 : "+f"(c0), "+f"(c1), "+f"(c2), "+f"(c3)
                 : "r"(a0), "r"(a1), "r"(a2), "r"(a3), "r"(b0), "r"(b1));
}

static __device__ __forceinline__ float ex2f(float x)
{
    float r; asm("ex2.approx.f32 %0, %1;" : "=f"(r) : "f"(x)); return r;
}

static __device__ __forceinline__ void fma2(unsigned long long& d,
                                            unsigned long long a,
                                            unsigned long long b)
{
    asm("fma.rn.f32x2 %0, %1, %2, %0;" : "+l"(d) : "l"(a), "l"(b));
}

static __device__ __forceinline__ unsigned long long splat2(float x)
{
    unsigned long long r;
    asm("mov.b64 %0, {%1, %1};" : "=l"(r) : "f"(x));
    return r;
}

static __device__ __forceinline__ float2 unpack2(unsigned long long v)
{
    float2 r;
    asm("mov.b64 {%0, %1}, %2;" : "=f"(r.x), "=f"(r.y) : "l"(v));
    return r;
}

__global__ __launch_bounds__(32)
void na3d_mma(const float* __restrict__ Q,
              const float* __restrict__ V,
              float* __restrict__ O)
{
    __shared__ __align__(16) float s_p[240 * 8];    // 7.68 KB probs (1 warp/CTA)

    const int lane = threadIdx.x;
    const int wg   = blockIdx.x;

    const int head = wg >> 11;
    const int rem  = wg & 2047;
    const int t    = rem >> 7;
    const int h0   = ((rem >> 3) & 15) * 2;
    const int w0   = (rem & 7) * 4;

    const int st = min(max(t - 1, 0), T_ - 3);
    const int bh = min(max(h0 - 3, 0), H_ - 8);
    const int bw = min(max(w0 - 3, 0), W_ - 10);

    const int g    = lane >> 2;
    const int tid4 = lane & 3;
    const int dh = g >> 2, dw = g & 3;
    const int shg = min(max(h0 + dh - 3, 0), H_ - 7);
    const int swg = min(max(w0 + dw - 3, 0), W_ - 7);

    unsigned wmask = 0;
    #pragma unroll
    for (int iw = 0; iw < 10; ++iw) {
        const int kw = bw + iw;
        if (kw >= swg && kw < swg + 7) wmask |= (1u << iw);
    }

    // ---- A fragments: this lane's query row (scaled), hi/lo split ----
    const float* qrow = Q + ((size_t)(t*1024 + (h0+dh)*32 + (w0+dw)) * 1024 + head*128);
    unsigned a0v[8], a1v[8], a2v[8], a3v[8];
    #pragma unroll
    for (int s = 0; s < 8; ++s) {
        const int d0 = s*16 + tid4*2;
        float2 f = *(const float2*)(qrow + d0);
        f.x *= QK_SCALE; f.y *= QK_SCALE;
        __half2 hi = __float22half2_rn(f);
        float2 hf = __half22float2(hi);
        __half2 lo = __float22half2_rn(make_float2(f.x - hf.x, f.y - hf.y));
        a0v[s] = *(unsigned*)&hi; a1v[s] = *(unsigned*)&lo;
        f = *(const float2*)(qrow + d0 + 8);
        f.x *= QK_SCALE; f.y *= QK_SCALE;
        hi = __float22half2_rn(f);
        hf = __half22float2(hi);
        lo = __float22half2_rn(make_float2(f.x - hf.x, f.y - hf.y));
        a2v[s] = *(unsigned*)&hi; a3v[s] = *(unsigned*)&lo;
    }

    float* sp = s_p;
    const uint2* kh_head = g_kh + (size_t)(head * 8) * L_ * 4;

    // ---------------- QK pass: 30 chunks of 8 keys, pipelined ----------------
    // load-key tracker (key index c*8 + g):
    int itL = 0, ihL = 0, iwL = g;        // g < 8 < 10, so starts in line 0
    // epilogue tracker (key index c*8 + 2*tid4; stays even, pairs never split lines)
    int ihE = 0, iwE = 2 * tid4;

    uint2 e[8];
    {
        const int lL = (st+itL)*1024 + (bh+ihL)*32 + (bw+iwL);
        const uint2* bp = kh_head + (size_t)lL*4 + tid4;
        #pragma unroll
        for (int s = 0; s < 8; ++s) e[s] = bp[(size_t)s * (L_*4)];
        iwL += 8; if (iwL >= 10) { iwL -= 10; if (++ihL >= 8) { ihL = 0; ++itL; } }
    }

    float lsum = 0.0f;
    int k0 = 2 * tid4;                    // epilogue key linear index
    #pragma unroll 1
    for (int c = 0; c < 30; ++c) {
        // next-chunk pointer (clamped in-bounds on the last iteration)
        const int lN = min((st+itL)*1024 + (bh+ihL)*32 + (bw+iwL), L_ - 1);
        const uint2* bpn = kh_head + (size_t)lN*4 + tid4;
        iwL += 8; if (iwL >= 10) { iwL -= 10; if (++ihL >= 8) { ihL = 0; ++itL; } }

        float c0 = 0.f, c1 = 0.f, c2 = 0.f, c3 = 0.f;
        #pragma unroll
        for (int s = 0; s < 8; ++s) {
            mma16816(c0,c1,c2,c3, a0v[s],a1v[s],a2v[s],a3v[s], e[s].x, e[s].y);
            e[s] = bpn[(size_t)s * (L_*4)];     // refill for chunk c+1
        }
        const float s0 = c0 + c2;   // score(g, key k0)
        const float s1 = c1 + c3;   // score(g, key k0+1)

        const bool vh = (unsigned)(bh + ihE - shg) < 7u;
        const float p0 = (vh && ((wmask >> iwE)       & 1u)) ? ex2f(s0) : 0.0f;
        const float p1 = (vh && ((wmask >> (iwE + 1)) & 1u)) ? ex2f(s1) : 0.0f;
        lsum += p0 + p1;
        sp[k0*8 + g]     = p0;
        sp[k0*8 + 8 + g] = p1;
        k0 += 8;
        iwE += 8; if (iwE >= 10) { iwE -= 10; if (++ihE >= 8) ihE = 0; }
    }
    __syncwarp();
    lsum += __shfl_xor_sync(~0u, lsum, 1);
    lsum += __shfl_xor_sync(~0u, lsum, 2);
    const float inv = 1.0f / lsum;

    // ---------------- PV pass: packed f32x2, query-paired accs ----------------
    const float4* __restrict__ V4 = (const float4*)V;
    float4* __restrict__ O4 = (float4*)O;
    const int qbase = (t*1024 + h0*32 + w0) * ROW4 + head*32 + lane;
    const int kbase = (st*1024 + bh*32 + bw) * ROW4 + head*32 + lane;

    unsigned long long acc[4][4];
    #pragma unroll
    for (int a = 0; a < 4; ++a)
        acc[a][0] = acc[a][1] = acc[a][2] = acc[a][3] = 0ull;

    int ridx8 = 0;
    #pragma unroll 1
    for (int it = 0; it < 3; ++it) {
        #pragma unroll 1
        for (int ih = 0; ih < 8; ++ih) {
            const int rowb = kbase + (it*1024 + ih*32) * ROW4;
            #pragma unroll 5
            for (int iw = 0; iw < 10; ++iw) {
                const ulonglong2 pA = *(const ulonglong2*)&sp[ridx8 + iw*8];
                const ulonglong2 pB = *(const ulonglong2*)&sp[ridx8 + iw*8 + 4];
                const float4 vv = V4[rowb + iw * ROW4];
                const unsigned long long vx = splat2(vv.x);
                const unsigned long long vy = splat2(vv.y);
                const unsigned long long vz = splat2(vv.z);
                const unsigned long long vw = splat2(vv.w);
                fma2(acc[0][0], pA.x, vx); fma2(acc[0][1], pA.x, vy);
                fma2(acc[0][2], pA.x, vz); fma2(acc[0][3], pA.x, vw);
                fma2(acc[1][0], pA.y, vx); fma2(acc[1][1], pA.y, vy);
                fma2(acc[1][2], pA.y, vz); fma2(acc[1][3], pA.y, vw);
                fma2(acc[2][0], pB.x, vx); fma2(acc[2][1], pB.x, vy);
                fma2(acc[2][2], pB.x, vz); fma2(acc[2][3], pB.x, vw);
                fma2(acc[3][0], pB.y, vx); fma2(acc[3][1], pB.y, vy);
                fma2(acc[3][2], pB.y, vz); fma2(acc[3][3], pB.y, vw);
            }
            ridx8 += 80;
        }
    }

    // ---------------- scale + store ----------------
    #pragma unroll
    for (int a = 0; a < 4; ++a) {
        const float iA = __shfl_sync(~0u, inv, (2*a)     << 2);
        const float iB = __shfl_sync(~0u, inv, (2*a + 1) << 2);
        const float2 d0 = unpack2(acc[a][0]);
        const float2 d1 = unpack2(acc[a][1]);
        const float2 d2 = unpack2(acc[a][2]);
        const float2 d3 = unpack2(acc[a][3]);
        float4 rA = make_float4(d0.x*iA, d1.x*iA, d2.x*iA, d3.x*iA);
        float4 rB = make_float4(d0.y*iB, d1.y*iB, d2.y*iB, d3.y*iB);
        const int jA = 2*a, jB = 2*a + 1;
        O4[qbase + ((jA >> 2)*32 + (jA & 3)) * ROW4] = rA;
        O4[qbase + ((jB >> 2)*32 + (jB & 3)) * ROW4] = rB;
    }
}

extern "C" void kernel_launch(void* const* d_in, const int* in_sizes, int n_in,
                              void* d_out, int out_size)
{
    const float* q = (const float*)d_in[0];
    const float* k = (const float*)d_in[1];
    const float* v = (const float*)d_in[2];
    float* out = (float*)d_out;

    prep_kh<<<4096, 256>>>(k);            // 1M threads
    na3d_mma<<<16384, 32>>>(q, v, out);   // 1 warp per CTA
}

// round 15
// speedup vs baseline: 1.1817x; 1.1817x over previous
#include <cuda_runtime.h>
#include <cuda_fp16.h>

// NeighborhoodAttention 3D, NATTEN clamped window (3,7,7).
// B=1, T=16, H=32, W=32, nh=8, D=128, fp32.
//
// Round 15 = Round 13 (block=128; QK tensor-core, q hi/lo exact x K_hi f16;
// max-free softmax; p in smem; PV exact fp32 packed fma.rn.f32x2) plus the
// two R14 improvements in isolation (WITHOUT the 32-thread-CTA change that
// regressed):
//  - QK software pipeline: e[s] refilled for chunk c+1 right after chunk c's
//    MMA consumes it (hides cross-chunk LDG latency, zero extra registers)
//  - incremental halo trackers instead of div/mod per chunk

#define T_  16
#define H_  32
#define W_  32
#define NH  8
#define L_  16384
#define ROW4 256
#define QK_SCALE (0.08838834764831845f * 1.4426950408889634f)  // /sqrt(128)*log2e

// K_hi packed: index ((head*8 + s)*L + l)*4 + p, uint2 = {b0, b1} of one MMA
__device__ uint2 g_kh[(size_t)NH * 8 * L_ * 4];   // 32 MB

__global__ __launch_bounds__(256)
void prep_kh(const float* __restrict__ K)
{
    const int tid = blockIdx.x * 256 + threadIdx.x;   // 1,048,576 threads
    const int l    = tid & (L_ - 1);
    const int hs   = tid >> 14;            // head*8 + s
    const int head = hs >> 3;
    const int s    = hs & 7;
    const float* src = K + ((size_t)l << 10) + (head << 7) + (s << 4);
    const float4 f0 = *(const float4*)(src);
    const float4 f1 = *(const float4*)(src + 4);
    const float4 f2 = *(const float4*)(src + 8);
    const float4 f3 = *(const float4*)(src + 12);

    uint2 e[4];
    __half2 h;
    h = __floats2half2_rn(f0.x, f0.y); e[0].x = *(unsigned*)&h;
    h = __floats2half2_rn(f2.x, f2.y); e[0].y = *(unsigned*)&h;
    h = __floats2half2_rn(f0.z, f0.w); e[1].x = *(unsigned*)&h;
    h = __floats2half2_rn(f2.z, f2.w); e[1].y = *(unsigned*)&h;
    h = __floats2half2_rn(f1.x, f1.y); e[2].x = *(unsigned*)&h;
    h = __floats2half2_rn(f3.x, f3.y); e[2].y = *(unsigned*)&h;
    h = __floats2half2_rn(f1.z, f1.w); e[3].x = *(unsigned*)&h;
    h = __floats2half2_rn(f3.z, f3.w); e[3].y = *(unsigned*)&h;

    uint4* dst = (uint4*)(g_kh + (size_t)tid * 4);
    dst[0] = *(uint4*)&e[0];
    dst[1] = *(uint4*)&e[2];
}

static __device__ __forceinline__ void mma16816(
    float& c0, float& c1, float& c2, float& c3,
    unsigned a0, unsigned a1, unsigned a2, unsigned a3,
    unsigned b0, unsigned b1)
{
    asm volatile("mma.sync.aligned.m16n8k16.row.col.f32.f16.f16.f32 "
                 "{%0,%1,%2,%3}, {%4,%5,%6,%7}, {%8,%9}, {%0,%1,%2,%3};"
                 : "+f"(c0), "+f"(c1), "+f"(c2), "+f"(c3)
                 : "r"(a0), "r"(a1), "r"(a2), "r"(a3), "r"(b0), "r"(b1));
}

static __device__ __forceinline__ float ex2f(float x)
{
    float r; asm("ex2.approx.f32 %0, %1;" : "=f"(r) : "f"(x)); return r;
}

static __device__ __forceinline__ void fma2(unsigned long long& d,
                                            unsigned long long a,
                                            unsigned long long b)
{
    asm("fma.rn.f32x2 %0, %1, %2, %0;" : "+l"(d) : "l"(a), "l"(b));
}

static __device__ __forceinline__ unsigned long long splat2(float x)
{
    unsigned long long r;
    asm("mov.b64 %0, {%1, %1};" : "=l"(r) : "f"(x));
    return r;
}

static __device__ __forceinline__ float2 unpack2(unsigned long long v)
{
    float2 r;
    asm("mov.b64 {%0, %1}, %2;" : "=f"(r.x), "=f"(r.y) : "l"(v));
    return r;
}

__global__ __launch_bounds__(128)
void na3d_mma(const float* __restrict__ Q,
              const float* __restrict__ V,
              float* __restrict__ O)
{
    __shared__ __align__(16) float s_p[4][240 * 8];    // 30 KB probs

    const int lane = threadIdx.x & 31;
    const int warp = threadIdx.x >> 5;
    const int wg   = blockIdx.x * 4 + warp;

    const int head = wg >> 11;
    const int rem  = wg & 2047;
    const int t    = rem >> 7;
    const int h0   = ((rem >> 3) & 15) * 2;
    const int w0   = (rem & 7) * 4;

    const int st = min(max(t - 1, 0), T_ - 3);
    const int bh = min(max(h0 - 3, 0), H_ - 8);
    const int bw = min(max(w0 - 3, 0), W_ - 10);

    const int g    = lane >> 2;
    const int tid4 = lane & 3;
    const int dh = g >> 2, dw = g & 3;
    const int shg = min(max(h0 + dh - 3, 0), H_ - 7);
    const int swg = min(max(w0 + dw - 3, 0), W_ - 7);

    unsigned wmask = 0;
    #pragma unroll
    for (int iw = 0; iw < 10; ++iw) {
        const int kw = bw + iw;
        if (kw >= swg && kw < swg + 7) wmask |= (1u << iw);
    }

    // ---- A fragments: this lane's query row (scaled), hi/lo split ----
    const float* qrow = Q + ((size_t)(t*1024 + (h0+dh)*32 + (w0+dw)) * 1024 + head*128);
    unsigned a0v[8], a1v[8], a2v[8], a3v[8];
    #pragma unroll
    for (int s = 0; s < 8; ++s) {
        const int d0 = s*16 + tid4*2;
        float2 f = *(const float2*)(qrow + d0);
        f.x *= QK_SCALE; f.y *= QK_SCALE;
        __half2 hi = __float22half2_rn(f);
        float2 hf = __half22float2(hi);
        __half2 lo = __float22half2_rn(make_float2(f.x - hf.x, f.y - hf.y));
        a0v[s] = *(unsigned*)&hi; a1v[s] = *(unsigned*)&lo;
        f = *(const float2*)(qrow + d0 + 8);
        f.x *= QK_SCALE; f.y *= QK_SCALE;
        hi = __float22half2_rn(f);
        hf = __half22float2(hi);
        lo = __float22half2_rn(make_float2(f.x - hf.x, f.y - hf.y));
        a2v[s] = *(unsigned*)&hi; a3v[s] = *(unsigned*)&lo;
    }

    float* sp = s_p[warp];
    const uint2* kh_head = g_kh + (size_t)(head * 8) * L_ * 4;

    // ---------------- QK pass: 30 chunks of 8 keys, pipelined ----------------
    int itL = 0, ihL = 0, iwL = g;        // load-key tracker (key c*8 + g)
    int ihE = 0, iwE = 2 * tid4;          // epilogue tracker (key c*8 + 2*tid4)

    uint2 e[8];
    {
        const int lL = (st+itL)*1024 + (bh+ihL)*32 + (bw+iwL);
        const uint2* bp = kh_head + (size_t)lL*4 + tid4;
        #pragma unroll
        for (int s = 0; s < 8; ++s) e[s] = bp[(size_t)s * (L_*4)];
        iwL += 8; if (iwL >= 10) { iwL -= 10; if (++ihL >= 8) { ihL = 0; ++itL; } }
    }

    float lsum = 0.0f;
    int k0 = 2 * tid4;                    // epilogue key linear index
    #pragma unroll 1
    for (int c = 0; c < 30; ++c) {
        // next-chunk pointer (clamped in-bounds on the last iteration)
        const int lN = min((st+itL)*1024 + (bh+ihL)*32 + (bw+iwL), L_ - 1);
        const uint2* bpn = kh_head + (size_t)lN*4 + tid4;
        iwL += 8; if (iwL >= 10) { iwL -= 10; if (++ihL >= 8) { ihL = 0; ++itL; } }

        float c0 = 0.f, c1 = 0.f, c2 = 0.f, c3 = 0.f;
        #pragma unroll
        for (int s = 0; s < 8; ++s) {
            mma16816(c0,c1,c2,c3, a0v[s],a1v[s],a2v[s],a3v[s], e[s].x, e[s].y);
            e[s] = bpn[(size_t)s * (L_*4)];     // refill for chunk c+1
        }
        const float s0 = c0 + c2;   // score(g, key k0)
        const float s1 = c1 + c3;   // score(g, key k0+1)

        const bool vh = (unsigned)(bh + ihE - shg) < 7u;
        const float p0 = (vh && ((wmask >> iwE)       & 1u)) ? ex2f(s0) : 0.0f;
        const float p1 = (vh && ((wmask >> (iwE + 1)) & 1u)) ? ex2f(s1) : 0.0f;
        lsum += p0 + p1;
        sp[k0*8 + g]     = p0;
        sp[k0*8 + 8 + g] = p1;
        k0 += 8;
        iwE += 8; if (iwE >= 10) { iwE -= 10; if (++ihE >= 8) ihE = 0; }
    }
    __syncwarp();
    lsum += __shfl_xor_sync(~0u, lsum, 1);
    lsum += __shfl_xor_sync(~0u, lsum, 2);
    const float inv = 1.0f / lsum;

    // ---------------- PV pass: packed f32x2, query-paired accs ----------------
    const float4* __restrict__ V4 = (const float4*)V;
    float4* __restrict__ O4 = (float4*)O;
    const int qbase = (t*1024 + h0*32 + w0) * ROW4 + head*32 + lane;
    const int kbase = (st*1024 + bh*32 + bw) * ROW4 + head*32 + lane;

    unsigned long long acc[4][4];
    #pragma unroll
    for (int a = 0; a < 4; ++a)
        acc[a][0] = acc[a][1] = acc[a][2] = acc[a][3] = 0ull;

    int ridx8 = 0;
    #pragma unroll 1
    for (int it = 0; it < 3; ++it) {
        #pragma unroll 1
        for (int ih = 0; ih < 8; ++ih) {
            const int rowb = kbase + (it*1024 + ih*32) * ROW4;
            #pragma unroll 5
            for (int iw = 0; iw < 10; ++iw) {
                const ulonglong2 pA = *(const ulonglong2*)&sp[ridx8 + iw*8];
                const ulonglong2 pB = *(const ulonglong2*)&sp[ridx8 + iw*8 + 4];
                const float4 vv = V4[rowb + iw * ROW4];
                const unsigned long long vx = splat2(vv.x);
                const unsigned long long vy = splat2(vv.y);
                const unsigned long long vz = splat2(vv.z);
                const unsigned long long vw = splat2(vv.w);
                fma2(acc[0][0], pA.x, vx); fma2(acc[0][1], pA.x, vy);
                fma2(acc[0][2], pA.x, vz); fma2(acc[0][3], pA.x, vw);
                fma2(acc[1][0], pA.y, vx); fma2(acc[1][1], pA.y, vy);
                fma2(acc[1][2], pA.y, vz); fma2(acc[1][3], pA.y, vw);
                fma2(acc[2][0], pB.x, vx); fma2(acc[2][1], pB.x, vy);
                fma2(acc[2][2], pB.x, vz); fma2(acc[2][3], pB.x, vw);
                fma2(acc[3][0], pB.y, vx); fma2(acc[3][1], pB.y, vy);
                fma2(acc[3][2], pB.y, vz); fma2(acc[3][3], pB.y, vw);
            }
            ridx8 += 80;
        }
    }

    // ---------------- scale + store ----------------
    #pragma unroll
    for (int a = 0; a < 4; ++a) {
        const float iA = __shfl_sync(~0u, inv, (2*a)     << 2);
        const float iB = __shfl_sync(~0u, inv, (2*a + 1) << 2);
        const float2 d0 = unpack2(acc[a][0]);
        const float2 d1 = unpack2(acc[a][1]);
        const float2 d2 = unpack2(acc[a][2]);
        const float2 d3 = unpack2(acc[a][3]);
        float4 rA = make_float4(d0.x*iA, d1.x*iA, d2.x*iA, d3.x*iA);
        float4 rB = make_float4(d0.y*iB, d1.y*iB, d2.y*iB, d3.y*iB);
        const int jA = 2*a, jB = 2*a + 1;
        O4[qbase + ((jA >> 2)*32 + (jA & 3)) * ROW4] = rA;
        O4[qbase + ((jB >> 2)*32 + (jB & 3)) * ROW4] = rB;
    }
}

extern "C" void kernel_launch(void* const* d_in, const int* in_sizes, int n_in,
                              void* d_out, int out_size)
{
    const float* q = (const float*)d_in[0];
    const float* k = (const float*)d_in[1];
    const float* v = (const float*)d_in[2];
    float* out = (float*)d_out;

    prep_kh<<<4096, 256>>>(k);           // 1M threads
    na3d_mma<<<4096, 128>>>(q, v, out);  // 4 warps per CTA (R13 config)
}